// round 1
// baseline (speedup 1.0000x reference)
#include <cuda_runtime.h>
#include <math.h>

// Problem constants (fixed shapes from reference setup_inputs)
constexpr int Bc = 64;      // batch
constexpr int Fc = 512;     // feature dim
constexpr int Sc = 8192;    // sign nodes
constexpr int Dc = 1024;    // diseases
constexpr float ETA = 0.01f;
constexpr float EPS = 1e-8f;

// Scratch (static __device__ globals — no allocations allowed)
__device__ float g_M[(size_t)Dc * Sc];   // 32 MB: M[d][s] = sum of edge weights
__device__ float g_sim[(size_t)Sc * Bc]; // 2 MB:  sim'[s][b] (fully scaled)
__device__ float g_sinv[Sc];             // 1/(||S_s||+eps)
__device__ float g_hinv[Bc];             // 1/(||H_b||+eps)
__device__ float g_gs[Bc];               // 0.5*ETA*||grad_b||

// ---------------------------------------------------------------------------
// Zero M and the output buffer (out is poisoned 0xAA by the harness).
// ---------------------------------------------------------------------------
__global__ void k_zero(float* __restrict__ out) {
    const size_t nM4   = ((size_t)Dc * Sc) / 4;
    const size_t nOut4 = ((size_t)Bc * Dc) / 4;
    float4 z = make_float4(0.f, 0.f, 0.f, 0.f);
    size_t stride = (size_t)gridDim.x * blockDim.x;
    size_t i = (size_t)blockIdx.x * blockDim.x + threadIdx.x;
    float4* pM = reinterpret_cast<float4*>(g_M);
    for (size_t j = i; j < nM4; j += stride) pM[j] = z;
    float4* pO = reinterpret_cast<float4*>(out);
    for (size_t j = i; j < nOut4; j += stride) pO[j] = z;
}

// ---------------------------------------------------------------------------
// Per-row norms of H (hinv) and grad (gs).  One block (128 thr) per row.
// ---------------------------------------------------------------------------
__global__ void k_hnorm(const float* __restrict__ H, const float* __restrict__ G) {
    int b = blockIdx.x;
    int t = threadIdx.x;           // 128 threads
    float s1 = 0.f, s2 = 0.f;
    for (int f = t; f < Fc; f += 128) {
        float h = H[(size_t)b * Fc + f];  s1 += h * h;
        float g = G[(size_t)b * Fc + f];  s2 += g * g;
    }
    __shared__ float r1[4], r2[4];
    #pragma unroll
    for (int o = 16; o; o >>= 1) {
        s1 += __shfl_xor_sync(0xffffffffu, s1, o);
        s2 += __shfl_xor_sync(0xffffffffu, s2, o);
    }
    if ((t & 31) == 0) { r1[t >> 5] = s1; r2[t >> 5] = s2; }
    __syncthreads();
    if (t == 0) {
        float n1 = sqrtf(r1[0] + r1[1] + r1[2] + r1[3]);
        float n2 = sqrtf(r2[0] + r2[1] + r2[2] + r2[3]);
        g_hinv[b] = 1.f / (n1 + EPS);
        g_gs[b]   = 0.5f * ETA * n2;
    }
}

// Per-row inverse norms of sign_features. One block (128 thr) per row.
__global__ void k_snorm(const float* __restrict__ Sg) {
    int s = blockIdx.x;
    int t = threadIdx.x;
    float acc = 0.f;
    for (int f = t; f < Fc; f += 128) {
        float v = Sg[(size_t)s * Fc + f];
        acc += v * v;
    }
    __shared__ float r[4];
    #pragma unroll
    for (int o = 16; o; o >>= 1) acc += __shfl_xor_sync(0xffffffffu, acc, o);
    if ((t & 31) == 0) r[t >> 5] = acc;
    __syncthreads();
    if (t == 0) g_sinv[s] = 1.f / (sqrtf(r[0] + r[1] + r[2] + r[3]) + EPS);
}

// ---------------------------------------------------------------------------
// Scatter edges into M:  M[disease][sign] += w.   500k atomics, ~6% collide.
// ---------------------------------------------------------------------------
__global__ void k_scatter(const float* __restrict__ w, const int* __restrict__ ed,
                          const int* __restrict__ es, int E) {
    int i = blockIdx.x * blockDim.x + threadIdx.x;
    int stride = gridDim.x * blockDim.x;
    for (; i < E; i += stride)
        atomicAdd(&g_M[(size_t)ed[i] * Sc + es[i]], w[i]);
}

// ---------------------------------------------------------------------------
// GEMM1: sim'[s][b] = gs[b] * ( (H_b . S_s) * hinv[b]*sinv[s] + 1 )
// Tile: 64 s x 64 b per block, 256 threads, 4x4 per thread, K-chunk 16.
// ---------------------------------------------------------------------------
__global__ void k_gemm1(const float* __restrict__ Hg, const float* __restrict__ Sg) {
    __shared__ float sS[16][68];   // [k][s-row]
    __shared__ float sH[16][68];   // [k][b-row]
    int t  = threadIdx.x;
    int s0 = blockIdx.x * 64;
    int tx = t & 15;               // -> b group
    int ty = t >> 4;               // -> s group
    float acc[4][4] = {};
    for (int kc = 0; kc < Fc; kc += 16) {
        #pragma unroll
        for (int i = 0; i < 4; i++) {
            int idx = t + i * 256;
            int r = idx >> 4, k = idx & 15;
            sS[k][r] = Sg[(size_t)(s0 + r) * Fc + kc + k];
            sH[k][r] = Hg[(size_t)r * Fc + kc + k];
        }
        __syncthreads();
        #pragma unroll
        for (int k = 0; k < 16; k++) {
            float a[4], bb[4];
            #pragma unroll
            for (int i = 0; i < 4; i++) { a[i] = sS[k][ty * 4 + i]; bb[i] = sH[k][tx * 4 + i]; }
            #pragma unroll
            for (int i = 0; i < 4; i++)
                #pragma unroll
                for (int j = 0; j < 4; j++) acc[i][j] += a[i] * bb[j];
        }
        __syncthreads();
    }
    #pragma unroll
    for (int i = 0; i < 4; i++) {
        int s = s0 + ty * 4 + i;
        float si = g_sinv[s];
        #pragma unroll
        for (int j = 0; j < 4; j++) {
            int b = tx * 4 + j;
            g_sim[(size_t)s * Bc + b] = g_gs[b] * (acc[i][j] * g_hinv[b] * si + 1.f);
        }
    }
}

// ---------------------------------------------------------------------------
// GEMM2: out[b][d] += sum_s sim'[s][b] * M[d][s]
// Grid: (Dc/64 d-tiles) x (Sc/512 k-splits). 256 thr, 4d x 4b per thread.
// Split-K partials land in d_out via atomicAdd (out pre-zeroed).
// ---------------------------------------------------------------------------
__global__ void k_gemm2(float* __restrict__ out) {
    __shared__ float sM[16][68];   // [k][d-row]
    __shared__ float sV[16][68];   // [k][b]
    int t  = threadIdx.x;
    int d0 = blockIdx.x * 64;
    int k0 = blockIdx.y * 512;
    int tx = t & 15;               // -> b group
    int ty = t >> 4;               // -> d group
    float acc[4][4] = {};
    for (int kc = 0; kc < 512; kc += 16) {
        #pragma unroll
        for (int i = 0; i < 4; i++) {
            int idx = t + i * 256;
            // M: k-fastest (16 contiguous floats per d-row -> 64B chunks)
            int r = idx >> 4, k = idx & 15;
            sM[k][r] = g_M[(size_t)(d0 + r) * Sc + k0 + kc + k];
            // sim: b-fastest (contiguous 256B rows -> fully coalesced)
            int rb = idx & 63, kb = idx >> 6;
            sV[kb][rb] = g_sim[(size_t)(k0 + kc + kb) * Bc + rb];
        }
        __syncthreads();
        #pragma unroll
        for (int k = 0; k < 16; k++) {
            float a[4], bb[4];
            #pragma unroll
            for (int i = 0; i < 4; i++) { a[i] = sM[k][ty * 4 + i]; bb[i] = sV[k][tx * 4 + i]; }
            #pragma unroll
            for (int i = 0; i < 4; i++)
                #pragma unroll
                for (int j = 0; j < 4; j++) acc[i][j] += a[i] * bb[j];
        }
        __syncthreads();
    }
    #pragma unroll
    for (int i = 0; i < 4; i++) {
        int d = d0 + ty * 4 + i;
        #pragma unroll
        for (int j = 0; j < 4; j++) {
            int b = tx * 4 + j;
            atomicAdd(&out[(size_t)b * Dc + d], acc[i][j]);
        }
    }
}

// ---------------------------------------------------------------------------
// Launch
// ---------------------------------------------------------------------------
extern "C" void kernel_launch(void* const* d_in, const int* in_sizes, int n_in,
                              void* d_out, int out_size) {
    const float* H  = (const float*)d_in[0];   // [64, 512]
    const float* G  = (const float*)d_in[1];   // [64, 512]
    const float* Sg = (const float*)d_in[2];   // [8192, 512]
    const float* w  = (const float*)d_in[3];   // [500000]
    const int*   ed = (const int*)d_in[4];     // [500000]
    const int*   es = (const int*)d_in[5];     // [500000]
    const int E = in_sizes[3];
    float* out = (float*)d_out;                // [64, 1024]

    k_zero<<<2048, 256>>>(out);
    k_hnorm<<<Bc, 128>>>(H, G);
    k_snorm<<<Sc, 128>>>(Sg);
    k_scatter<<<(E + 255) / 256, 256>>>(w, ed, es, E);
    k_gemm1<<<Sc / 64, 256>>>(H, Sg);
    dim3 g2(Dc / 64, Sc / 512);
    k_gemm2<<<g2, 256>>>(out);
}

// round 3
// speedup vs baseline: 1.9747x; 1.9747x over previous
#include <cuda_runtime.h>
#include <cuda_bf16.h>
#include <math.h>
#include <stdint.h>

// Fixed shapes from reference setup_inputs
constexpr int Bc = 64;      // batch
constexpr int Fc = 512;     // feature dim
constexpr int Sc = 8192;    // sign nodes
constexpr int Dc = 1024;    // diseases
constexpr float ETA = 0.01f;
constexpr float EPS = 1e-8f;

// Scratch (__device__ globals — no allocations allowed)
__device__ __nv_bfloat16 g_Mb[(size_t)Dc * Sc];   // 16 MB: M[d][s] bf16
__device__ __nv_bfloat16 g_simb[(size_t)Bc * Sc]; // 1 MB:  sim'[b][s] bf16 (K-major for GEMM2)
__device__ __nv_bfloat16 g_Hb[Bc * Fc];           // H bf16 (K-major)
__device__ __nv_bfloat16 g_Sb[(size_t)Sc * Fc];   // S bf16 (K-major)
__device__ float g_sinv[Sc];
__device__ float g_hinv[Bc];
__device__ float g_gs[Bc];

// ---------------------------------------------------------------------------
// Helpers: ldmatrix + mma.sync (baseline PTX — works at compute_103)
// ---------------------------------------------------------------------------
__device__ __forceinline__ uint32_t smem_u32(const void* p) {
    uint32_t a;
    asm("{ .reg .u64 t; cvta.to.shared.u64 t, %1; cvt.u32.u64 %0, t; }" : "=r"(a) : "l"(p));
    return a;
}
__device__ __forceinline__ uint32_t sw128(uint32_t b) { return b ^ ((b >> 3) & 0x70); }

__device__ __forceinline__ void ldsm_x4(uint32_t& r0, uint32_t& r1, uint32_t& r2, uint32_t& r3,
                                        uint32_t addr) {
    asm volatile("ldmatrix.sync.aligned.m8n8.x4.shared.b16 {%0,%1,%2,%3}, [%4];"
                 : "=r"(r0), "=r"(r1), "=r"(r2), "=r"(r3) : "r"(addr));
}
__device__ __forceinline__ void mma16816(float* c, uint32_t a0, uint32_t a1, uint32_t a2,
                                         uint32_t a3, uint32_t b0, uint32_t b1) {
    asm volatile(
        "mma.sync.aligned.m16n8k16.row.col.f32.bf16.bf16.f32 "
        "{%0,%1,%2,%3}, {%4,%5,%6,%7}, {%8,%9}, {%0,%1,%2,%3};"
        : "+f"(c[0]), "+f"(c[1]), "+f"(c[2]), "+f"(c[3])
        : "r"(a0), "r"(a1), "r"(a2), "r"(a3), "r"(b0), "r"(b1));
}

// Shared 64x64 K-chunked mma core. A[64 rows, K], B[64 rows, K], K-major bf16.
// 128 threads / 4 warps; warp w computes rows [w*16, w*16+16) x all 64 B-rows.
// acc[g][4]: g indexes the 8 n-groups of 8 columns.
__device__ __forceinline__ void mma_chunk(char* tA, char* tB, float acc[8][4]) {
    uint32_t sa = smem_u32(tA), sb = smem_u32(tB);
    int lane = threadIdx.x & 31, wid = threadIdx.x >> 5;
    #pragma unroll
    for (int ks = 0; ks < 4; ks++) {
        uint32_t a0, a1, a2, a3;
        ldsm_x4(a0, a1, a2, a3,
                sa + sw128((wid * 16 + (lane & 15)) * 128 + (ks * 2 + (lane >> 4)) * 16));
        #pragma unroll
        for (int g = 0; g < 8; g += 2) {
            uint32_t b0, b1, b2, b3;
            ldsm_x4(b0, b1, b2, b3,
                    sb + sw128(((g + (lane >> 4)) * 8 + (lane & 7)) * 128 +
                               (ks * 2 + ((lane >> 3) & 1)) * 16));
            mma16816(acc[g],     a0, a1, a2, a3, b0, b1);
            mma16816(acc[g + 1], a0, a1, a2, a3, b2, b3);
        }
    }
}

// Stage one 64x64 bf16 tile (row-major, K-fastest) into SW128 smem. 128 thr.
__device__ __forceinline__ void stage_tile(char* dst, const __nv_bfloat16* src,
                                           size_t ld, int row0, int kc) {
    int t = threadIdx.x;
    #pragma unroll
    for (int i = 0; i < 4; i++) {
        int j = i * 128 + t, row = j >> 3, col = j & 7;
        *reinterpret_cast<uint4*>(dst + sw128(row * 128 + col * 16)) =
            *reinterpret_cast<const uint4*>(src + (size_t)(row0 + row) * ld + kc + col * 8);
    }
}

// ---------------------------------------------------------------------------
// Zero g_Mb (16MB bf16) and out (256KB).
// ---------------------------------------------------------------------------
__global__ void k_zero(float* __restrict__ out) {
    const size_t nM4 = ((size_t)Dc * Sc * 2) / 16;
    const size_t nO4 = ((size_t)Bc * Dc) / 4;
    uint4 z = make_uint4(0, 0, 0, 0);
    size_t stride = (size_t)gridDim.x * blockDim.x;
    size_t i = (size_t)blockIdx.x * blockDim.x + threadIdx.x;
    uint4* pM = reinterpret_cast<uint4*>(g_Mb);
    for (size_t j = i; j < nM4; j += stride) pM[j] = z;
    float4* pO = reinterpret_cast<float4*>(out);
    float4 zf = make_float4(0.f, 0.f, 0.f, 0.f);
    for (size_t j = i; j < nO4; j += stride) pO[j] = zf;
}

// ---------------------------------------------------------------------------
// Prep H: hinv, gs, H->bf16. One block / batch row.
// ---------------------------------------------------------------------------
__global__ void k_prepH(const float* __restrict__ H, const float* __restrict__ G) {
    int b = blockIdx.x, t = threadIdx.x;  // 128 threads
    float s1 = 0.f, s2 = 0.f;
    #pragma unroll
    for (int i = 0; i < 4; i++) {
        int f = t + i * 128;
        float h = H[(size_t)b * Fc + f];
        float g = G[(size_t)b * Fc + f];
        s1 += h * h; s2 += g * g;
        g_Hb[(size_t)b * Fc + f] = __float2bfloat16(h);
    }
    __shared__ float r1[4], r2[4];
    #pragma unroll
    for (int o = 16; o; o >>= 1) {
        s1 += __shfl_xor_sync(0xffffffffu, s1, o);
        s2 += __shfl_xor_sync(0xffffffffu, s2, o);
    }
    if ((t & 31) == 0) { r1[t >> 5] = s1; r2[t >> 5] = s2; }
    __syncthreads();
    if (t == 0) {
        g_hinv[b] = 1.f / (sqrtf(r1[0] + r1[1] + r1[2] + r1[3]) + EPS);
        g_gs[b]   = 0.5f * ETA * sqrtf(r2[0] + r2[1] + r2[2] + r2[3]);
    }
}

// Prep S: sinv + S->bf16. One block / sign row.
__global__ void k_prepS(const float* __restrict__ Sg) {
    int s = blockIdx.x, t = threadIdx.x;  // 128 threads
    float acc = 0.f;
    #pragma unroll
    for (int i = 0; i < 4; i++) {
        int f = t + i * 128;
        float v = Sg[(size_t)s * Fc + f];
        acc += v * v;
        g_Sb[(size_t)s * Fc + f] = __float2bfloat16(v);
    }
    __shared__ float r[4];
    #pragma unroll
    for (int o = 16; o; o >>= 1) acc += __shfl_xor_sync(0xffffffffu, acc, o);
    if ((t & 31) == 0) r[t >> 5] = acc;
    __syncthreads();
    if (t == 0) g_sinv[s] = 1.f / (sqrtf(r[0] + r[1] + r[2] + r[3]) + EPS);
}

// ---------------------------------------------------------------------------
// Scatter edges into bf16 M: red.global.add.noftz.bf16
// ---------------------------------------------------------------------------
__global__ void k_scatter(const float* __restrict__ w, const int* __restrict__ ed,
                          const int* __restrict__ es, int E) {
    int i = blockIdx.x * blockDim.x + threadIdx.x;
    int stride = gridDim.x * blockDim.x;
    for (; i < E; i += stride) {
        __nv_bfloat16 wb = __float2bfloat16(w[i]);
        unsigned short u = *reinterpret_cast<unsigned short*>(&wb);
        __nv_bfloat16* addr = &g_Mb[(size_t)ed[i] * Sc + es[i]];
        asm volatile("red.global.add.noftz.bf16 [%0], %1;" :: "l"(addr), "h"(u) : "memory");
    }
}

// ---------------------------------------------------------------------------
// GEMM1: acc[s 64][b 64] = S·Hᵀ over K=512; epilogue scales, writes sim'[b][s].
// Grid: 128 CTAs (s-tiles of 64) x 128 threads.
// ---------------------------------------------------------------------------
__global__ void __launch_bounds__(128) k_gemm1() {
    __shared__ alignas(1024) char tA[8192];
    __shared__ alignas(1024) char tB[8192];
    __shared__ float sh_hinv[64], sh_gs[64];
    int t = threadIdx.x, lane = t & 31, wid = t >> 5;
    if (t < 64) { sh_hinv[t] = g_hinv[t]; sh_gs[t] = g_gs[t]; }
    int s0 = blockIdx.x * 64;
    float acc[8][4] = {};
    for (int c = 0; c < Fc / 64; c++) {
        stage_tile(tA, g_Sb, Fc, s0, c * 64);
        stage_tile(tB, g_Hb, Fc, 0, c * 64);
        __syncthreads();
        mma_chunk(tA, tB, acc);
        __syncthreads();
    }
    int gr = lane >> 2, tig = lane & 3;
    int sr = s0 + wid * 16 + gr;
    float si0 = g_sinv[sr], si1 = g_sinv[sr + 8];
    #pragma unroll
    for (int g = 0; g < 8; g++) {
        int b = g * 8 + tig * 2;
        float h0 = sh_hinv[b], h1 = sh_hinv[b + 1];
        float w0 = sh_gs[b],   w1 = sh_gs[b + 1];
        g_simb[(size_t)b       * Sc + sr    ] = __float2bfloat16(w0 * (acc[g][0] * h0 * si0 + 1.f));
        g_simb[(size_t)(b + 1) * Sc + sr    ] = __float2bfloat16(w1 * (acc[g][1] * h1 * si0 + 1.f));
        g_simb[(size_t)b       * Sc + sr + 8] = __float2bfloat16(w0 * (acc[g][2] * h0 * si1 + 1.f));
        g_simb[(size_t)(b + 1) * Sc + sr + 8] = __float2bfloat16(w1 * (acc[g][3] * h1 * si1 + 1.f));
    }
}

// ---------------------------------------------------------------------------
// GEMM2: out[b][d] += sum_s M[d,s]*sim'[b,s]. Split-K.
// Grid: (16 d-tiles of 64) x (16 k-splits of 512), 128 threads.
// ---------------------------------------------------------------------------
__global__ void __launch_bounds__(128) k_gemm2(float* __restrict__ out) {
    __shared__ alignas(1024) char tA[8192];
    __shared__ alignas(1024) char tB[8192];
    int t = threadIdx.x, lane = t & 31, wid = t >> 5;
    int d0 = blockIdx.x * 64;
    int kbase = blockIdx.y * 512;
    float acc[8][4] = {};
    for (int c = 0; c < 8; c++) {
        stage_tile(tA, g_Mb, Sc, d0, kbase + c * 64);
        stage_tile(tB, g_simb, Sc, 0, kbase + c * 64);
        __syncthreads();
        mma_chunk(tA, tB, acc);
        __syncthreads();
    }
    int gr = lane >> 2, tig = lane & 3;
    int dr = d0 + wid * 16 + gr;
    #pragma unroll
    for (int g = 0; g < 8; g++) {
        int b = g * 8 + tig * 2;
        atomicAdd(&out[(size_t)b       * Dc + dr    ], acc[g][0]);
        atomicAdd(&out[(size_t)(b + 1) * Dc + dr    ], acc[g][1]);
        atomicAdd(&out[(size_t)b       * Dc + dr + 8], acc[g][2]);
        atomicAdd(&out[(size_t)(b + 1) * Dc + dr + 8], acc[g][3]);
    }
}

// ---------------------------------------------------------------------------
// Launch
// ---------------------------------------------------------------------------
extern "C" void kernel_launch(void* const* d_in, const int* in_sizes, int n_in,
                              void* d_out, int out_size) {
    const float* H  = (const float*)d_in[0];   // [64, 512]
    const float* G  = (const float*)d_in[1];   // [64, 512]
    const float* Sg = (const float*)d_in[2];   // [8192, 512]
    const float* w  = (const float*)d_in[3];   // [500000]
    const int*   ed = (const int*)d_in[4];
    const int*   es = (const int*)d_in[5];
    const int E = in_sizes[3];
    float* out = (float*)d_out;                // [64, 1024]

    k_zero<<<2048, 256>>>(out);
    k_prepH<<<Bc, 128>>>(H, G);
    k_prepS<<<Sc, 128>>>(Sg);
    k_scatter<<<(E + 255) / 256, 256>>>(w, ed, es, E);
    k_gemm1<<<Sc / 64, 128>>>();
    dim3 g2(Dc / 64, 16);
    k_gemm2<<<g2, 128>>>(out);
}

// round 6
// speedup vs baseline: 2.7064x; 1.3705x over previous
#include <cuda_runtime.h>
#include <cuda_bf16.h>
#include <math.h>
#include <stdint.h>

// Fixed shapes from reference setup_inputs
constexpr int Bc = 64;      // batch
constexpr int Fc = 512;     // feature dim
constexpr int Sc = 8192;    // sign nodes
constexpr int Dc = 1024;    // diseases
constexpr float ETA = 0.01f;
constexpr float EPS = 1e-8f;

// Scratch (__device__ globals — no allocations allowed)
__device__ __nv_bfloat16 g_Mb[(size_t)Dc * Sc];   // 16 MB: M[d][s] bf16
__device__ __nv_bfloat16 g_simb[(size_t)Bc * Sc]; // 1 MB:  sim'[b][s] bf16 (K-major for GEMM2)
__device__ __nv_bfloat16 g_Hb[Bc * Fc];           // H bf16 (K-major)
__device__ __nv_bfloat16 g_Sb[(size_t)Sc * Fc];   // S bf16 (K-major)
__device__ float g_sinv[Sc];
__device__ float g_hinv[Bc];
__device__ float g_gs[Bc];

// ---------------------------------------------------------------------------
// Helpers (baseline PTX only — must compile at compute_103)
// ---------------------------------------------------------------------------
__device__ __forceinline__ uint32_t smem_u32(const void* p) {
    uint32_t a;
    asm("{ .reg .u64 t; cvta.to.shared.u64 t, %1; cvt.u32.u64 %0, t; }" : "=r"(a) : "l"(p));
    return a;
}
__device__ __forceinline__ uint32_t sw128(uint32_t b) { return b ^ ((b >> 3) & 0x70); }

__device__ __forceinline__ void ldsm_x4(uint32_t& r0, uint32_t& r1, uint32_t& r2, uint32_t& r3,
                                        uint32_t addr) {
    asm volatile("ldmatrix.sync.aligned.m8n8.x4.shared.b16 {%0,%1,%2,%3}, [%4];"
                 : "=r"(r0), "=r"(r1), "=r"(r2), "=r"(r3) : "r"(addr));
}
__device__ __forceinline__ void mma16816(float* c, uint32_t a0, uint32_t a1, uint32_t a2,
                                         uint32_t a3, uint32_t b0, uint32_t b1) {
    asm volatile(
        "mma.sync.aligned.m16n8k16.row.col.f32.bf16.bf16.f32 "
        "{%0,%1,%2,%3}, {%4,%5,%6,%7}, {%8,%9}, {%0,%1,%2,%3};"
        : "+f"(c[0]), "+f"(c[1]), "+f"(c[2]), "+f"(c[3])
        : "r"(a0), "r"(a1), "r"(a2), "r"(a3), "r"(b0), "r"(b1));
}

#define CP_ASYNC16(dst, src) \
    asm volatile("cp.async.cg.shared.global [%0], [%1], 16;" :: "r"(dst), "l"(src))
#define CP_COMMIT()   asm volatile("cp.async.commit_group;" ::: "memory")
#define CP_WAIT(n)    asm volatile("cp.async.wait_group %0;" :: "n"(n) : "memory")

// 64x64 K-chunked mma core. A[64, K], B[64, K], K-major bf16 in SW128 smem.
// 128 threads / 4 warps; warp w computes A-rows [w*16, w*16+16) x all 64 B-rows.
__device__ __forceinline__ void mma_chunk(const char* tA, const char* tB, float acc[8][4]) {
    uint32_t sa = smem_u32(tA), sb = smem_u32(tB);
    int lane = threadIdx.x & 31, wid = threadIdx.x >> 5;
    #pragma unroll
    for (int ks = 0; ks < 4; ks++) {
        uint32_t a0, a1, a2, a3;
        ldsm_x4(a0, a1, a2, a3,
                sa + sw128((wid * 16 + (lane & 15)) * 128 + (ks * 2 + (lane >> 4)) * 16));
        #pragma unroll
        for (int g = 0; g < 8; g += 2) {
            uint32_t b0, b1, b2, b3;
            ldsm_x4(b0, b1, b2, b3,
                    sb + sw128(((g + (lane >> 4)) * 8 + (lane & 7)) * 128 +
                               (ks * 2 + ((lane >> 3) & 1)) * 16));
            mma16816(acc[g],     a0, a1, a2, a3, b0, b1);
            mma16816(acc[g + 1], a0, a1, a2, a3, b2, b3);
        }
    }
}

// Stage one 64x64 bf16 tile into SW128 smem, synchronous uint4 loads. 128 thr.
__device__ __forceinline__ void stage_tile(char* dst, const __nv_bfloat16* src,
                                           size_t ld, int row0, int kc) {
    int t = threadIdx.x;
    #pragma unroll
    for (int i = 0; i < 4; i++) {
        int j = i * 128 + t, row = j >> 3, col = j & 7;
        *reinterpret_cast<uint4*>(dst + sw128(row * 128 + col * 16)) =
            *reinterpret_cast<const uint4*>(src + (size_t)(row0 + row) * ld + kc + col * 8);
    }
}

// Same, but cp.async (for the double-buffered GEMM2 pipeline).
__device__ __forceinline__ void stage_async(char* dst, const __nv_bfloat16* src,
                                            size_t ld, int row0, int kc) {
    int t = threadIdx.x;
    uint32_t sd = smem_u32(dst);
    #pragma unroll
    for (int i = 0; i < 4; i++) {
        int j = i * 128 + t, row = j >> 3, col = j & 7;
        const void* g = src + (size_t)(row0 + row) * ld + kc + col * 8;
        CP_ASYNC16(sd + sw128(row * 128 + col * 16), g);
    }
}

// ---------------------------------------------------------------------------
// K1: zero M + out, prepH, prepS — one fused kernel, 128 threads/block.
//   bid [0, 8192)        : prepS row
//   bid [8192, 8256)     : prepH row
//   bid [8256, 8256+2048): zero stripes
// ---------------------------------------------------------------------------
constexpr int K1_ZB = 2048;
__global__ void __launch_bounds__(128) k_prep(const float* __restrict__ H,
                                              const float* __restrict__ G,
                                              const float* __restrict__ Sg,
                                              float* __restrict__ out) {
    int bid = blockIdx.x, t = threadIdx.x;
    if (bid < Sc) {                       // ---- prepS
        int s = bid;
        float acc = 0.f;
        #pragma unroll
        for (int i = 0; i < 4; i++) {
            int f = t + i * 128;
            float v = Sg[(size_t)s * Fc + f];
            acc += v * v;
            g_Sb[(size_t)s * Fc + f] = __float2bfloat16(v);
        }
        __shared__ float r[4];
        #pragma unroll
        for (int o = 16; o; o >>= 1) acc += __shfl_xor_sync(0xffffffffu, acc, o);
        if ((t & 31) == 0) r[t >> 5] = acc;
        __syncthreads();
        if (t == 0) g_sinv[s] = 1.f / (sqrtf(r[0] + r[1] + r[2] + r[3]) + EPS);
    } else if (bid < Sc + Bc) {           // ---- prepH
        int b = bid - Sc;
        float s1 = 0.f, s2 = 0.f;
        #pragma unroll
        for (int i = 0; i < 4; i++) {
            int f = t + i * 128;
            float h = H[(size_t)b * Fc + f];
            float g = G[(size_t)b * Fc + f];
            s1 += h * h; s2 += g * g;
            g_Hb[(size_t)b * Fc + f] = __float2bfloat16(h);
        }
        __shared__ float r1[4], r2[4];
        #pragma unroll
        for (int o = 16; o; o >>= 1) {
            s1 += __shfl_xor_sync(0xffffffffu, s1, o);
            s2 += __shfl_xor_sync(0xffffffffu, s2, o);
        }
        if ((t & 31) == 0) { r1[t >> 5] = s1; r2[t >> 5] = s2; }
        __syncthreads();
        if (t == 0) {
            g_hinv[b] = 1.f / (sqrtf(r1[0] + r1[1] + r1[2] + r1[3]) + EPS);
            g_gs[b]   = 0.5f * ETA * sqrtf(r2[0] + r2[1] + r2[2] + r2[3]);
        }
    } else {                              // ---- zero M (16MB) + out (256KB)
        size_t z = (size_t)(bid - Sc - Bc) * 128 + t;
        size_t stride = (size_t)K1_ZB * 128;
        const size_t nM4 = ((size_t)Dc * Sc * 2) / 16;
        uint4* pM = reinterpret_cast<uint4*>(g_Mb);
        uint4 zz = make_uint4(0, 0, 0, 0);
        for (size_t j = z; j < nM4; j += stride) pM[j] = zz;
        const size_t nO4 = ((size_t)Bc * Dc) / 4;
        float4* pO = reinterpret_cast<float4*>(out);
        float4 zf = make_float4(0.f, 0.f, 0.f, 0.f);
        for (size_t j = z; j < nO4; j += stride) pO[j] = zf;
    }
}

// ---------------------------------------------------------------------------
// K2: scatter (blocks [0, SCAT_B)) fused with GEMM1 (blocks [SCAT_B, +128)).
// Scatter: 32-bit bf16x2 red with zero in the unused lane (full-word atomic
// rate; bf16 x+0 == x exactly, all values >= 0).
// GEMM1: acc[s 64][b 64] = S·Hᵀ over K=512; epilogue scales -> sim'[b][s].
// ---------------------------------------------------------------------------
constexpr int Ec = 500000;
constexpr int SCAT_B = (Ec + 127) / 128;   // 3907
__global__ void __launch_bounds__(128) k_mid(const float* __restrict__ w,
                                             const int* __restrict__ ed,
                                             const int* __restrict__ es, int E) {
    __shared__ alignas(1024) char tA[8192];
    __shared__ alignas(1024) char tB[8192];
    __shared__ float sh_hinv[64], sh_gs[64];
    int t = threadIdx.x;
    if ((int)blockIdx.x < SCAT_B) {       // ---- scatter
        int i = blockIdx.x * 128 + t;
        if (i < E) {
            __nv_bfloat16 wb = __float2bfloat16(w[i]);
            uint32_t u = (uint32_t)*reinterpret_cast<unsigned short*>(&wb);
            size_t idx = (size_t)ed[i] * Sc + es[i];
            uint32_t val = (idx & 1) ? (u << 16) : u;
            uint32_t* addr = reinterpret_cast<uint32_t*>(g_Mb + (idx & ~(size_t)1));
            asm volatile("red.global.add.noftz.bf16x2 [%0], %1;" :: "l"(addr), "r"(val) : "memory");
        }
        return;
    }
    // ---- gemm1
    int lane = t & 31, wid = t >> 5;
    if (t < 64) { sh_hinv[t] = g_hinv[t]; sh_gs[t] = g_gs[t]; }
    int s0 = (blockIdx.x - SCAT_B) * 64;
    float acc[8][4] = {};
    for (int c = 0; c < Fc / 64; c++) {
        stage_tile(tA, g_Sb, Fc, s0, c * 64);
        stage_tile(tB, g_Hb, Fc, 0, c * 64);
        __syncthreads();
        mma_chunk(tA, tB, acc);
        __syncthreads();
    }
    int gr = lane >> 2, tig = lane & 3;
    int sr = s0 + wid * 16 + gr;
    float si0 = g_sinv[sr], si1 = g_sinv[sr + 8];
    #pragma unroll
    for (int g = 0; g < 8; g++) {
        int b = g * 8 + tig * 2;
        float h0 = sh_hinv[b], h1 = sh_hinv[b + 1];
        float w0 = sh_gs[b],   w1 = sh_gs[b + 1];
        g_simb[(size_t)b       * Sc + sr    ] = __float2bfloat16(w0 * (acc[g][0] * h0 * si0 + 1.f));
        g_simb[(size_t)(b + 1) * Sc + sr    ] = __float2bfloat16(w1 * (acc[g][1] * h1 * si0 + 1.f));
        g_simb[(size_t)b       * Sc + sr + 8] = __float2bfloat16(w0 * (acc[g][2] * h0 * si1 + 1.f));
        g_simb[(size_t)(b + 1) * Sc + sr + 8] = __float2bfloat16(w1 * (acc[g][3] * h1 * si1 + 1.f));
    }
}

// ---------------------------------------------------------------------------
// K3: GEMM2, double-buffered cp.async. out[b][d] += sum_s M[d,s]*sim'[b,s].
// Grid: (16 d-tiles of 64) x (8 k-splits of 1024), 128 threads.
// ---------------------------------------------------------------------------
__global__ void __launch_bounds__(128) k_gemm2(float* __restrict__ out) {
    __shared__ alignas(1024) char tA[2][8192];
    __shared__ alignas(1024) char tB[2][8192];
    int t = threadIdx.x, lane = t & 31, wid = t >> 5;
    int d0 = blockIdx.x * 64;
    int kbase = blockIdx.y * 1024;
    float acc[8][4] = {};

    stage_async(tA[0], g_Mb,   Sc, d0, kbase);
    stage_async(tB[0], g_simb, Sc, 0,  kbase);
    CP_COMMIT();

    #pragma unroll 1
    for (int c = 0; c < 16; c++) {
        int cb = c & 1;
        if (c < 15) {
            stage_async(tA[cb ^ 1], g_Mb,   Sc, d0, kbase + (c + 1) * 64);
            stage_async(tB[cb ^ 1], g_simb, Sc, 0,  kbase + (c + 1) * 64);
            CP_COMMIT();
            CP_WAIT(1);
        } else {
            CP_WAIT(0);
        }
        __syncthreads();
        mma_chunk(tA[cb], tB[cb], acc);
        __syncthreads();
    }
    int gr = lane >> 2, tig = lane & 3;
    int dr = d0 + wid * 16 + gr;
    #pragma unroll
    for (int g = 0; g < 8; g++) {
        int b = g * 8 + tig * 2;
        atomicAdd(&out[(size_t)b       * Dc + dr    ], acc[g][0]);
        atomicAdd(&out[(size_t)(b + 1) * Dc + dr    ], acc[g][1]);
        atomicAdd(&out[(size_t)b       * Dc + dr + 8], acc[g][2]);
        atomicAdd(&out[(size_t)(b + 1) * Dc + dr + 8], acc[g][3]);
    }
}

// ---------------------------------------------------------------------------
// Launch: 3 kernels.
// ---------------------------------------------------------------------------
extern "C" void kernel_launch(void* const* d_in, const int* in_sizes, int n_in,
                              void* d_out, int out_size) {
    const float* H  = (const float*)d_in[0];   // [64, 512]
    const float* G  = (const float*)d_in[1];   // [64, 512]
    const float* Sg = (const float*)d_in[2];   // [8192, 512]
    const float* w  = (const float*)d_in[3];   // [500000]
    const int*   ed = (const int*)d_in[4];
    const int*   es = (const int*)d_in[5];
    const int E = in_sizes[3];
    float* out = (float*)d_out;                // [64, 1024]

    k_prep<<<Sc + Bc + K1_ZB, 128>>>(H, G, Sg, out);
    k_mid<<<SCAT_B + Sc / 64, 128>>>(w, ed, es, E);
    dim3 g2(Dc / 64, 8);
    k_gemm2<<<g2, 128>>>(out);
}